// round 4
// baseline (speedup 1.0000x reference)
#include <cuda_runtime.h>
#include <cuda_bf16.h>
#include <cstdint>

// Problem dims
#define DB 32
#define DT 64
#define DV 50257
#define DE 256
#define DH 512
#define G4H 2048   // 4*H
#define H2  1024   // 2*H
#define NROWS 2048 // T*B

// ---------------- scratch (device globals; no allocations allowed) ----------
__device__ float g_xgates[DT * DB * G4H];  // [t*B+b, 4H]
__device__ float g_hgates[DB * G4H];       // [b, 4H]
__device__ float g_hs[DT * DB * DH];       // [t*B+b, H]
__device__ float g_hid[DT * DB * H2];      // [t*B+b, 2H]

// ---------------- mma.sync helpers (sm_80+ HMMA path; valid on sm_103) ------
__device__ __forceinline__ uint32_t smem_to_u32(const void* smem_ptr) {
    uint32_t addr;
    asm("{ .reg .u64 tmp; cvta.to.shared.u64 tmp, %1; cvt.u32.u64 %0, tmp; }"
        : "=r"(addr) : "l"(smem_ptr));
    return addr;
}

__device__ __forceinline__ void ldmx4(uint32_t* r, uint32_t addr) {
    asm volatile("ldmatrix.sync.aligned.m8n8.x4.shared.b16 {%0,%1,%2,%3}, [%4];"
                 : "=r"(r[0]), "=r"(r[1]), "=r"(r[2]), "=r"(r[3]) : "r"(addr));
}

__device__ __forceinline__ void mma16816(float* c, const uint32_t* a, const uint32_t* b) {
    asm volatile(
        "mma.sync.aligned.m16n8k16.row.col.f32.bf16.bf16.f32 "
        "{%0,%1,%2,%3}, {%4,%5,%6,%7}, {%8,%9}, {%0,%1,%2,%3};"
        : "+f"(c[0]), "+f"(c[1]), "+f"(c[2]), "+f"(c[3])
        : "r"(a[0]), "r"(a[1]), "r"(a[2]), "r"(a[3]), "r"(b[0]), "r"(b[1]));
}

__device__ __forceinline__ uint32_t pack2bf(__nv_bfloat16 a, __nv_bfloat16 b) {
    return ((uint32_t)__bfloat16_as_ushort(b) << 16) | (uint32_t)__bfloat16_as_ushort(a);
}

// ---------------- SIMT tiled GEMM: C[m,n] = sum_k A[m,k]*B[n,k] + bias[n] ----
// GATHER: A row m -> emb[ token(b = m%32, t = m/32) ] with teacher-forcing shift
#define SG_BM 64
#define SG_BN 64
#define SG_BK 16

template <bool GATHER>
__global__ __launch_bounds__(256) void sgemm_atbt(
    const float* __restrict__ A, const float* __restrict__ Bw,
    const float* __restrict__ bias, float* __restrict__ C,
    int M, int N, int K, const int* __restrict__ captions)
{
    __shared__ float As[SG_BK][SG_BM + 1];
    __shared__ float Bs[SG_BK][SG_BN + 1];
    const int m0 = blockIdx.y * SG_BM;
    const int n0 = blockIdx.x * SG_BN;
    const int tid = threadIdx.x;
    const int tx = tid & 15, ty = tid >> 4;
    const int arow = tid >> 2;   // 0..63
    const int aq = tid & 3;      // float4 index within 16-wide K tile

    float acc[4][4];
#pragma unroll
    for (int i = 0; i < 4; i++)
#pragma unroll
        for (int j = 0; j < 4; j++) acc[i][j] = 0.f;

    int gm = m0 + arow;
    if (gm > M - 1) gm = M - 1;     // clamp for M < tile (h_gates case)
    const float* aptr;
    if (GATHER) {
        int t = gm >> 5;             // /B
        int b = gm & 31;
        int tt = (t == 0) ? 0 : (t - 1);
        int tok = captions[b * DT + tt];
        aptr = A + (size_t)tok * K;
    } else {
        aptr = A + (size_t)gm * K;
    }
    const float* bptr = Bw + (size_t)(n0 + arow) * K;

    for (int k0 = 0; k0 < K; k0 += SG_BK) {
        float4 av = *(const float4*)(aptr + k0 + aq * 4);
        float4 bv = *(const float4*)(bptr + k0 + aq * 4);
        __syncthreads();
        As[aq * 4 + 0][arow] = av.x; As[aq * 4 + 1][arow] = av.y;
        As[aq * 4 + 2][arow] = av.z; As[aq * 4 + 3][arow] = av.w;
        Bs[aq * 4 + 0][arow] = bv.x; Bs[aq * 4 + 1][arow] = bv.y;
        Bs[aq * 4 + 2][arow] = bv.z; Bs[aq * 4 + 3][arow] = bv.w;
        __syncthreads();
#pragma unroll
        for (int k = 0; k < SG_BK; k++) {
            float a[4], b[4];
#pragma unroll
            for (int i = 0; i < 4; i++) a[i] = As[k][ty * 4 + i];
#pragma unroll
            for (int j = 0; j < 4; j++) b[j] = Bs[k][tx * 4 + j];
#pragma unroll
            for (int i = 0; i < 4; i++)
#pragma unroll
                for (int j = 0; j < 4; j++) acc[i][j] += a[i] * b[j];
        }
    }

#pragma unroll
    for (int i = 0; i < 4; i++) {
        int m = m0 + ty * 4 + i;
        if (m >= M) continue;
#pragma unroll
        for (int j = 0; j < 4; j++) {
            int n = n0 + tx * 4 + j;
            C[(size_t)m * N + n] = acc[i][j] + bias[n];
        }
    }
}

// ---------------- LSTM scan (elementwise; gates fully precomputed) ----------
__global__ __launch_bounds__(256) void lstm_scan_kernel() {
    int idx = blockIdx.x * 256 + threadIdx.x;  // 0..16383
    int b = idx >> 9;        // /H
    int h = idx & (DH - 1);
    const float* hgp = g_hgates + b * G4H;
    float hgi = hgp[h], hgf = hgp[DH + h], hgg = hgp[2 * DH + h], hgo = hgp[3 * DH + h];
    float c = 0.f;
#pragma unroll 1
    for (int t = 0; t < DT; t++) {
        const float* x = g_xgates + (size_t)(t * DB + b) * G4H;
        float gi = x[h] + hgi;
        float gf = x[DH + h] + hgf;
        float gg = x[2 * DH + h] + hgg;
        float go = x[3 * DH + h] + hgo;
        float si = 1.f / (1.f + expf(-gi));
        float sf = 1.f / (1.f + expf(-gf));
        float so = 1.f / (1.f + expf(-go));
        c = sf * c + si * tanhf(gg);
        g_hs[(size_t)(t * DB + b) * DH + h] = so * tanhf(c);
    }
}

// ---------------- big logits GEMM: mma.sync bf16 hi/lo 3-pass ----------------
// C[m, v] = sum_k hid[m,k]*W2[v,k] + b2[v], out[(b*T+t)*V + v], m = t*B + b
// CTA tile 128x128, K-chunk 32; 8 warps (2x4) of 64x32 each; padded SMEM +
// ldmatrix (conflict-free at stride 40 elems = 80 B).
#define BM 128
#define BN 128
#define BK 32
#define SAPAD 40

__global__ __launch_bounds__(256) void logits_mma_kernel(
    const float* __restrict__ W2, const float* __restrict__ b2,
    float* __restrict__ out)
{
    __shared__ __align__(16) __nv_bfloat16 sAhi[BM * SAPAD];
    __shared__ __align__(16) __nv_bfloat16 sAlo[BM * SAPAD];
    __shared__ __align__(16) __nv_bfloat16 sBhi[BN * SAPAD];
    __shared__ __align__(16) __nv_bfloat16 sBlo[BN * SAPAD];

    const int tid = threadIdx.x;
    const int wid = tid >> 5, lane = tid & 31;
    const int m0 = blockIdx.x * BM;
    const int n0 = blockIdx.y * BN;
    const int wm = (wid & 1) * 64;     // warp m-offset within tile
    const int wn = (wid >> 1) * 32;    // warp n-offset within tile

    float acc[4][4][4];
#pragma unroll
    for (int mi = 0; mi < 4; mi++)
#pragma unroll
        for (int ni = 0; ni < 4; ni++)
#pragma unroll
            for (int f = 0; f < 4; f++) acc[mi][ni][f] = 0.f;

    const int lrow = tid >> 3;        // 0..31 (loader row base)
    const int lq = (tid & 7) * 4;     // loader col (floats)

    const uint32_t uAhi = smem_to_u32(sAhi);
    const uint32_t uAlo = smem_to_u32(sAlo);
    const uint32_t uBhi = smem_to_u32(sBhi);
    const uint32_t uBlo = smem_to_u32(sBlo);

    // ldmatrix lane addressing (byte offsets into a [rows][SAPAD] bf16 tile)
    const int a_r = lane & 15;               // row within 16-row A block
    const int a_c = (lane >> 4) * 8;         // 0 or 8 (k-half)
    const int b_g = lane >> 3;               // 0..3
    const int b_r = (lane & 7) + ((b_g >> 1) * 8);
    const int b_c = (b_g & 1) * 8;

#pragma unroll 1
    for (int k0 = 0; k0 < H2; k0 += BK) {
        __syncthreads();   // previous compute done before overwrite
        // ---- load fp32, split to bf16 hi/lo, store swizzle-free padded ----
#pragma unroll
        for (int rr = 0; rr < 4; rr++) {
            int row = lrow + rr * 32;
            // A = hid tile
            float4 av = *(const float4*)(g_hid + (size_t)(m0 + row) * H2 + k0 + lq);
            // B = W2 tile (zero-pad beyond vocab)
            int brow = n0 + row;
            float4 bv = make_float4(0.f, 0.f, 0.f, 0.f);
            if (brow < DV) bv = *(const float4*)(W2 + (size_t)brow * H2 + k0 + lq);

            __nv_bfloat16 ahx = __float2bfloat16(av.x), ahy = __float2bfloat16(av.y);
            __nv_bfloat16 ahz = __float2bfloat16(av.z), ahw = __float2bfloat16(av.w);
            uint2 ah = make_uint2(pack2bf(ahx, ahy), pack2bf(ahz, ahw));
            uint2 al = make_uint2(
                pack2bf(__float2bfloat16(av.x - __bfloat162float(ahx)),
                        __float2bfloat16(av.y - __bfloat162float(ahy))),
                pack2bf(__float2bfloat16(av.z - __bfloat162float(ahz)),
                        __float2bfloat16(av.w - __bfloat162float(ahw))));
            __nv_bfloat16 bhx = __float2bfloat16(bv.x), bhy = __float2bfloat16(bv.y);
            __nv_bfloat16 bhz = __float2bfloat16(bv.z), bhw = __float2bfloat16(bv.w);
            uint2 bh = make_uint2(pack2bf(bhx, bhy), pack2bf(bhz, bhw));
            uint2 bl = make_uint2(
                pack2bf(__float2bfloat16(bv.x - __bfloat162float(bhx)),
                        __float2bfloat16(bv.y - __bfloat162float(bhy))),
                pack2bf(__float2bfloat16(bv.z - __bfloat162float(bhz)),
                        __float2bfloat16(bv.w - __bfloat162float(bhw))));

            int so = row * SAPAD + lq;
            *(uint2*)(sAhi + so) = ah;
            *(uint2*)(sAlo + so) = al;
            *(uint2*)(sBhi + so) = bh;
            *(uint2*)(sBlo + so) = bl;
        }
        __syncthreads();

        // ---- compute: 2 x k16 steps, 3-pass hi/lo ----
#pragma unroll
        for (int kk = 0; kk < BK; kk += 16) {
            uint32_t ah[4][4], al[4][4], bh[4][2], bl[4][2];
#pragma unroll
            for (int mi = 0; mi < 4; mi++) {
                uint32_t off = (uint32_t)(((wm + mi * 16 + a_r) * SAPAD + kk + a_c) * 2);
                ldmx4(ah[mi], uAhi + off);
                ldmx4(al[mi], uAlo + off);
            }
#pragma unroll
            for (int nb = 0; nb < 2; nb++) {
                uint32_t off = (uint32_t)(((wn + nb * 16 + b_r) * SAPAD + kk + b_c) * 2);
                uint32_t t0[4], t1[4];
                ldmx4(t0, uBhi + off);
                ldmx4(t1, uBlo + off);
                bh[2 * nb][0] = t0[0]; bh[2 * nb][1] = t0[1];
                bh[2 * nb + 1][0] = t0[2]; bh[2 * nb + 1][1] = t0[3];
                bl[2 * nb][0] = t1[0]; bl[2 * nb][1] = t1[1];
                bl[2 * nb + 1][0] = t1[2]; bl[2 * nb + 1][1] = t1[3];
            }
#pragma unroll
            for (int mi = 0; mi < 4; mi++)
#pragma unroll
                for (int ni = 0; ni < 4; ni++) {
                    mma16816(acc[mi][ni], ah[mi], bh[ni]);
                    mma16816(acc[mi][ni], ah[mi], bl[ni]);
                    mma16816(acc[mi][ni], al[mi], bh[ni]);
                }
        }
    }

    // ---- epilogue: scatter to out[(b*T+t)*V + v] with b2 -------------------
    // NOTE: DV is odd -> row bases alternate parity; 32-bit stores only.
    const int gr = lane >> 2;           // 0..7
    const int gc = (lane & 3) * 2;
#pragma unroll
    for (int mi = 0; mi < 4; mi++) {
#pragma unroll
        for (int half = 0; half < 2; half++) {
            int m = m0 + wm + mi * 16 + gr + half * 8;
            int t = m >> 5, b = m & 31;
            float* orow = out + (size_t)(b * DT + t) * DV;
#pragma unroll
            for (int ni = 0; ni < 4; ni++) {
                int v = n0 + wn + ni * 8 + gc;
                float c0 = acc[mi][ni][half * 2 + 0];
                float c1 = acc[mi][ni][half * 2 + 1];
                if (v < DV)     orow[v]     = c0 + b2[v];
                if (v + 1 < DV) orow[v + 1] = c1 + b2[v + 1];
            }
        }
    }
}

// ---------------- launch ----------------------------------------------------
extern "C" void kernel_launch(void* const* d_in, const int* in_sizes, int n_in,
                              void* d_out, int out_size) {
    const float* features = (const float*)d_in[0];
    const int*   captions = (const int*)d_in[1];
    const float* emb      = (const float*)d_in[2];
    const float* W_ih     = (const float*)d_in[3];
    const float* W_hh     = (const float*)d_in[4];
    const float* b_ih     = (const float*)d_in[5];
    const float* b_hh     = (const float*)d_in[6];
    const float* W1       = (const float*)d_in[7];
    const float* b1       = (const float*)d_in[8];
    const float* W2       = (const float*)d_in[9];
    const float* b2       = (const float*)d_in[10];
    float* out = (float*)d_out;

    float *xg_p, *hg_p, *hs_p, *hid_p;
    cudaGetSymbolAddress((void**)&xg_p,  g_xgates);
    cudaGetSymbolAddress((void**)&hg_p,  g_hgates);
    cudaGetSymbolAddress((void**)&hs_p,  g_hs);
    cudaGetSymbolAddress((void**)&hid_p, g_hid);

    // 1) x_gates[t*B+b, 4H] = emb[tok(b,t)] @ W_ih^T + b_ih   (2048x2048, K=256)
    sgemm_atbt<true><<<dim3(G4H / SG_BN, NROWS / SG_BM), 256>>>(
        emb, W_ih, b_ih, xg_p, NROWS, G4H, DE, captions);

    // 2) h_gates[b, 4H] = features @ W_hh^T + b_hh            (32x2048, K=512)
    sgemm_atbt<false><<<dim3(G4H / SG_BN, 1), 256>>>(
        features, W_hh, b_hh, hg_p, DB, G4H, DH, nullptr);

    // 3) LSTM cell scan (elementwise over (B,H), T steps)
    lstm_scan_kernel<<<DB * DH / 256, 256>>>();

    // 4) hid[t*B+b, 2H] = hs @ W1^T + b1                      (2048x1024, K=512)
    sgemm_atbt<false><<<dim3(H2 / SG_BN, NROWS / SG_BM), 256>>>(
        hs_p, W1, b1, hid_p, NROWS, H2, DH, nullptr);

    // 5) logits = hid @ W2^T + b2  (mma.sync bf16 3-pass hi/lo split)
    logits_mma_kernel<<<dim3(NROWS / BM, (DV + BN - 1) / BN), 256>>>(W2, b2, out);
}

// round 5
// speedup vs baseline: 1.0942x; 1.0942x over previous
#include <cuda_runtime.h>
#include <cuda_bf16.h>
#include <cstdint>

// Problem dims
#define DB 32
#define DT 64
#define DV 50257
#define DVP 50304   // padded vocab (393 * 128)
#define DE 256
#define DH 512
#define G4H 2048   // 4*H
#define H2  1024   // 2*H
#define NROWS 2048 // T*B

// ---------------- scratch (device globals; no allocations allowed) ----------
__device__ float g_xgates[DT * DB * G4H];  // [t*B+b, 4H]
__device__ float g_hgates[DB * G4H];       // [b, 4H]
__device__ float g_hs[DT * DB * DH];       // [t*B+b, H]
__device__ float g_hid[DT * DB * H2];      // [t*B+b, 2H]
// bf16 hi/lo pre-converted operands for the big GEMM
__device__ __nv_bfloat16 g_W2hi[(size_t)DVP * H2];
__device__ __nv_bfloat16 g_W2lo[(size_t)DVP * H2];
__device__ __nv_bfloat16 g_hidhi[(size_t)NROWS * H2];
__device__ __nv_bfloat16 g_hidlo[(size_t)NROWS * H2];

// ---------------- helpers ----------------------------------------------------
__device__ __forceinline__ uint32_t smem_to_u32(const void* smem_ptr) {
    uint32_t addr;
    asm("{ .reg .u64 tmp; cvta.to.shared.u64 tmp, %1; cvt.u32.u64 %0, tmp; }"
        : "=r"(addr) : "l"(smem_ptr));
    return addr;
}

__device__ __forceinline__ void ldmx4(uint32_t* r, uint32_t addr) {
    asm volatile("ldmatrix.sync.aligned.m8n8.x4.shared.b16 {%0,%1,%2,%3}, [%4];"
                 : "=r"(r[0]), "=r"(r[1]), "=r"(r[2]), "=r"(r[3]) : "r"(addr));
}

__device__ __forceinline__ void mma16816(float* c, const uint32_t* a, const uint32_t* b) {
    asm volatile(
        "mma.sync.aligned.m16n8k16.row.col.f32.bf16.bf16.f32 "
        "{%0,%1,%2,%3}, {%4,%5,%6,%7}, {%8,%9}, {%0,%1,%2,%3};"
        : "+f"(c[0]), "+f"(c[1]), "+f"(c[2]), "+f"(c[3])
        : "r"(a[0]), "r"(a[1]), "r"(a[2]), "r"(a[3]), "r"(b[0]), "r"(b[1]));
}

__device__ __forceinline__ uint32_t pack2bf(__nv_bfloat16 a, __nv_bfloat16 b) {
    return ((uint32_t)__bfloat16_as_ushort(b) << 16) | (uint32_t)__bfloat16_as_ushort(a);
}

__device__ __forceinline__ void cp_async16(uint32_t saddr, const void* gaddr) {
    asm volatile("cp.async.cg.shared.global [%0], [%1], 16;"
                 :: "r"(saddr), "l"(gaddr));
}

// XOR swizzle for 64-B rows of 16-B chunks: conflict-free for cp.async stores
// (8 consecutive rows x 4 chunks per warp) and ldmatrix reads (8 rows, fixed chunk).
__device__ __forceinline__ uint32_t swz(int row, int chunk) {
    return (uint32_t)(row * 64 + ((chunk ^ ((row >> 1) & 3)) << 4));
}

// ---------------- SIMT tiled GEMM: C[m,n] = sum_k A[m,k]*B[n,k] + bias[n] ----
#define SG_BM 64
#define SG_BN 64
#define SG_BK 16

template <bool GATHER>
__global__ __launch_bounds__(256) void sgemm_atbt(
    const float* __restrict__ A, const float* __restrict__ Bw,
    const float* __restrict__ bias, float* __restrict__ C,
    int M, int N, int K, const int* __restrict__ captions)
{
    __shared__ float As[SG_BK][SG_BM + 1];
    __shared__ float Bs[SG_BK][SG_BN + 1];
    const int m0 = blockIdx.y * SG_BM;
    const int n0 = blockIdx.x * SG_BN;
    const int tid = threadIdx.x;
    const int tx = tid & 15, ty = tid >> 4;
    const int arow = tid >> 2;
    const int aq = tid & 3;

    float acc[4][4];
#pragma unroll
    for (int i = 0; i < 4; i++)
#pragma unroll
        for (int j = 0; j < 4; j++) acc[i][j] = 0.f;

    int gm = m0 + arow;
    if (gm > M - 1) gm = M - 1;
    const float* aptr;
    if (GATHER) {
        int t = gm >> 5;
        int b = gm & 31;
        int tt = (t == 0) ? 0 : (t - 1);
        int tok = captions[b * DT + tt];
        aptr = A + (size_t)tok * K;
    } else {
        aptr = A + (size_t)gm * K;
    }
    const float* bptr = Bw + (size_t)(n0 + arow) * K;

    for (int k0 = 0; k0 < K; k0 += SG_BK) {
        float4 av = *(const float4*)(aptr + k0 + aq * 4);
        float4 bv = *(const float4*)(bptr + k0 + aq * 4);
        __syncthreads();
        As[aq * 4 + 0][arow] = av.x; As[aq * 4 + 1][arow] = av.y;
        As[aq * 4 + 2][arow] = av.z; As[aq * 4 + 3][arow] = av.w;
        Bs[aq * 4 + 0][arow] = bv.x; Bs[aq * 4 + 1][arow] = bv.y;
        Bs[aq * 4 + 2][arow] = bv.z; Bs[aq * 4 + 3][arow] = bv.w;
        __syncthreads();
#pragma unroll
        for (int k = 0; k < SG_BK; k++) {
            float a[4], b[4];
#pragma unroll
            for (int i = 0; i < 4; i++) a[i] = As[k][ty * 4 + i];
#pragma unroll
            for (int j = 0; j < 4; j++) b[j] = Bs[k][tx * 4 + j];
#pragma unroll
            for (int i = 0; i < 4; i++)
#pragma unroll
                for (int j = 0; j < 4; j++) acc[i][j] += a[i] * b[j];
        }
    }

#pragma unroll
    for (int i = 0; i < 4; i++) {
        int m = m0 + ty * 4 + i;
        if (m >= M) continue;
#pragma unroll
        for (int j = 0; j < 4; j++) {
            int n = n0 + tx * 4 + j;
            C[(size_t)m * N + n] = acc[i][j] + bias[n];
        }
    }
}

// ---------------- LSTM scan ---------------------------------------------------
__global__ __launch_bounds__(256) void lstm_scan_kernel() {
    int idx = blockIdx.x * 256 + threadIdx.x;
    int b = idx >> 9;
    int h = idx & (DH - 1);
    const float* hgp = g_hgates + b * G4H;
    float hgi = hgp[h], hgf = hgp[DH + h], hgg = hgp[2 * DH + h], hgo = hgp[3 * DH + h];
    float c = 0.f;
#pragma unroll 1
    for (int t = 0; t < DT; t++) {
        const float* x = g_xgates + (size_t)(t * DB + b) * G4H;
        float gi = x[h] + hgi;
        float gf = x[DH + h] + hgf;
        float gg = x[2 * DH + h] + hgg;
        float go = x[3 * DH + h] + hgo;
        float si = 1.f / (1.f + expf(-gi));
        float sf = 1.f / (1.f + expf(-gf));
        float so = 1.f / (1.f + expf(-go));
        c = sf * c + si * tanhf(gg);
        g_hs[(size_t)(t * DB + b) * DH + h] = so * tanhf(c);
    }
}

// ---------------- fp32 -> bf16 hi/lo pre-conversion ---------------------------
// One block per row of 1024 elems; 256 threads x float4.
__global__ __launch_bounds__(256) void convert_w2_kernel(const float* __restrict__ W2) {
    int row = blockIdx.x;                // 0..DVP-1
    int q = threadIdx.x * 4;             // elem offset in row
    size_t o = (size_t)row * H2 + q;
    float4 v = make_float4(0.f, 0.f, 0.f, 0.f);
    if (row < DV) v = *(const float4*)(W2 + o);
    __nv_bfloat16 hx = __float2bfloat16(v.x), hy = __float2bfloat16(v.y);
    __nv_bfloat16 hz = __float2bfloat16(v.z), hw = __float2bfloat16(v.w);
    uint2 hi = make_uint2(pack2bf(hx, hy), pack2bf(hz, hw));
    uint2 lo = make_uint2(
        pack2bf(__float2bfloat16(v.x - __bfloat162float(hx)),
                __float2bfloat16(v.y - __bfloat162float(hy))),
        pack2bf(__float2bfloat16(v.z - __bfloat162float(hz)),
                __float2bfloat16(v.w - __bfloat162float(hw))));
    *(uint2*)(g_W2hi + o) = hi;
    *(uint2*)(g_W2lo + o) = lo;
}

__global__ __launch_bounds__(256) void convert_hid_kernel() {
    int row = blockIdx.x;                // 0..NROWS-1
    int q = threadIdx.x * 4;
    size_t o = (size_t)row * H2 + q;
    float4 v = *(const float4*)(g_hid + o);
    __nv_bfloat16 hx = __float2bfloat16(v.x), hy = __float2bfloat16(v.y);
    __nv_bfloat16 hz = __float2bfloat16(v.z), hw = __float2bfloat16(v.w);
    uint2 hi = make_uint2(pack2bf(hx, hy), pack2bf(hz, hw));
    uint2 lo = make_uint2(
        pack2bf(__float2bfloat16(v.x - __bfloat162float(hx)),
                __float2bfloat16(v.y - __bfloat162float(hy))),
        pack2bf(__float2bfloat16(v.z - __bfloat162float(hz)),
                __float2bfloat16(v.w - __bfloat162float(hw))));
    *(uint2*)(g_hidhi + o) = hi;
    *(uint2*)(g_hidlo + o) = lo;
}

// ---------------- big logits GEMM: cp.async pipelined, bf16 hi/lo 3-pass ------
// C[m, v] = sum_k hid[m,k]*W2[v,k] + b2[v], out[(b*T+t)*V + v], m = t*B + b
#define BM 128
#define BN 128
#define BK 32
#define NT (H2 / BK)          // 32 K-tiles
// per-stage SMEM layout (bytes): Ahi 8K | Alo 8K | Bhi 8K | Blo 8K = 32 KB
#define ST_ALO 8192
#define ST_BHI 16384
#define ST_BLO 24576
#define STAGE_BYTES 32768
#define SMEM_BIG (2 * STAGE_BYTES)

__global__ __launch_bounds__(256) void logits_mma_kernel(
    const float* __restrict__ b2, float* __restrict__ out)
{
    extern __shared__ __align__(128) char smem[];
    const uint32_t sb0 = smem_to_u32(smem);
    const int tid = threadIdx.x;
    const int wid = tid >> 5, lane = tid & 31;
    const int m0 = blockIdx.x * BM;
    const int n0 = blockIdx.y * BN;
    const int wm = (wid & 1) * 64;
    const int wn = (wid >> 1) * 32;

    float acc[4][4][4];
#pragma unroll
    for (int mi = 0; mi < 4; mi++)
#pragma unroll
        for (int ni = 0; ni < 4; ni++)
#pragma unroll
            for (int f = 0; f < 4; f++) acc[mi][ni][f] = 0.f;

    // loader mapping: lane-in-block t -> (row = t>>2 [+64], chunk = t&3)
    const int lrow = tid >> 2;         // 0..63
    const int lc = tid & 3;
    // gmem bases for this CTA's row stripes (bf16 elems)
    const __nv_bfloat16* gAhi = g_hidhi + (size_t)m0 * H2;
    const __nv_bfloat16* gAlo = g_hidlo + (size_t)m0 * H2;
    const __nv_bfloat16* gBhi = g_W2hi + (size_t)n0 * H2;
    const __nv_bfloat16* gBlo = g_W2lo + (size_t)n0 * H2;

    // ldmatrix lane addressing
    const int a_r = lane & 15;
    const int a_cb = lane >> 4;            // chunk base 0/1
    const int b_g = lane >> 3;
    const int b_r = (lane & 7) + ((b_g >> 1) * 8);
    const int b_cb = b_g & 1;

    // ---- stage loader (8 cp.async of 16 B per thread) ----
    auto issue_stage = [&](int s) {
        const uint32_t base = sb0 + (uint32_t)(s & 1) * STAGE_BYTES;
        const int k0 = s * BK;             // elem offset
#pragma unroll
        for (int j = 0; j < 2; j++) {
            int row = lrow + j * 64;
            uint32_t so = swz(row, lc);
            size_t go = (size_t)row * H2 + k0 + lc * 8;
            cp_async16(base + so,            gAhi + go);
            cp_async16(base + ST_ALO + so,   gAlo + go);
            cp_async16(base + ST_BHI + so,   gBhi + go);
            cp_async16(base + ST_BLO + so,   gBlo + go);
        }
        asm volatile("cp.async.commit_group;");
    };

    issue_stage(0);

#pragma unroll 1
    for (int s = 0; s < NT; s++) {
        if (s + 1 < NT) {
            issue_stage(s + 1);
            asm volatile("cp.async.wait_group 1;");
        } else {
            asm volatile("cp.async.wait_group 0;");
        }
        __syncthreads();

        const uint32_t base = sb0 + (uint32_t)(s & 1) * STAGE_BYTES;
#pragma unroll
        for (int kk = 0; kk < BK; kk += 16) {
            const int cb = kk >> 3;        // 0 or 2
            uint32_t ah[4][4], al[4][4], bh[4][2], bl[4][2];
#pragma unroll
            for (int mi = 0; mi < 4; mi++) {
                int row = wm + mi * 16 + a_r;
                uint32_t off = swz(row, cb + a_cb);
                ldmx4(ah[mi], base + off);
                ldmx4(al[mi], base + ST_ALO + off);
            }
#pragma unroll
            for (int nb = 0; nb < 2; nb++) {
                int row = wn + nb * 16 + b_r;
                uint32_t off = swz(row, cb + b_cb);
                uint32_t t0[4], t1[4];
                ldmx4(t0, base + ST_BHI + off);
                ldmx4(t1, base + ST_BLO + off);
                bh[2 * nb][0] = t0[0]; bh[2 * nb][1] = t0[1];
                bh[2 * nb + 1][0] = t0[2]; bh[2 * nb + 1][1] = t0[3];
                bl[2 * nb][0] = t1[0]; bl[2 * nb][1] = t1[1];
                bl[2 * nb + 1][0] = t1[2]; bl[2 * nb + 1][1] = t1[3];
            }
#pragma unroll
            for (int mi = 0; mi < 4; mi++)
#pragma unroll
                for (int ni = 0; ni < 4; ni++) {
                    mma16816(acc[mi][ni], ah[mi], bh[ni]);
                    mma16816(acc[mi][ni], ah[mi], bl[ni]);
                    mma16816(acc[mi][ni], al[mi], bh[ni]);
                }
        }
        __syncthreads();
    }

    // ---- epilogue: scatter to out[(b*T+t)*V + v] with b2 ----
    // DV odd -> row bases alternate parity; 32-bit stores only.
    const int gr = lane >> 2;
    const int gc = (lane & 3) * 2;
#pragma unroll
    for (int mi = 0; mi < 4; mi++) {
#pragma unroll
        for (int half = 0; half < 2; half++) {
            int m = m0 + wm + mi * 16 + gr + half * 8;
            int t = m >> 5, b = m & 31;
            float* orow = out + (size_t)(b * DT + t) * DV;
#pragma unroll
            for (int ni = 0; ni < 4; ni++) {
                int v = n0 + wn + ni * 8 + gc;
                float c0 = acc[mi][ni][half * 2 + 0];
                float c1 = acc[mi][ni][half * 2 + 1];
                if (v < DV)     orow[v]     = c0 + b2[v];
                if (v + 1 < DV) orow[v + 1] = c1 + b2[v + 1];
            }
        }
    }
}

// ---------------- launch ----------------------------------------------------
extern "C" void kernel_launch(void* const* d_in, const int* in_sizes, int n_in,
                              void* d_out, int out_size) {
    const float* features = (const float*)d_in[0];
    const int*   captions = (const int*)d_in[1];
    const float* emb      = (const float*)d_in[2];
    const float* W_ih     = (const float*)d_in[3];
    const float* W_hh     = (const float*)d_in[4];
    const float* b_ih     = (const float*)d_in[5];
    const float* b_hh     = (const float*)d_in[6];
    const float* W1       = (const float*)d_in[7];
    const float* b1       = (const float*)d_in[8];
    const float* W2       = (const float*)d_in[9];
    const float* b2       = (const float*)d_in[10];
    float* out = (float*)d_out;

    float *xg_p, *hg_p, *hs_p, *hid_p;
    cudaGetSymbolAddress((void**)&xg_p,  g_xgates);
    cudaGetSymbolAddress((void**)&hg_p,  g_hgates);
    cudaGetSymbolAddress((void**)&hs_p,  g_hs);
    cudaGetSymbolAddress((void**)&hid_p, g_hid);

    // 0) W2 -> bf16 hi/lo (padded to DVP rows)
    convert_w2_kernel<<<DVP, 256>>>(W2);

    // 1) x_gates = emb[tok] @ W_ih^T + b_ih   (2048x2048, K=256)
    sgemm_atbt<true><<<dim3(G4H / SG_BN, NROWS / SG_BM), 256>>>(
        emb, W_ih, b_ih, xg_p, NROWS, G4H, DE, captions);

    // 2) h_gates = features @ W_hh^T + b_hh   (32x2048, K=512)
    sgemm_atbt<false><<<dim3(G4H / SG_BN, 1), 256>>>(
        features, W_hh, b_hh, hg_p, DB, G4H, DH, nullptr);

    // 3) LSTM cell scan
    lstm_scan_kernel<<<DB * DH / 256, 256>>>();

    // 4) hid = hs @ W1^T + b1                 (2048x1024, K=512)
    sgemm_atbt<false><<<dim3(H2 / SG_BN, NROWS / SG_BM), 256>>>(
        hs_p, W1, b1, hid_p, NROWS, H2, DH, nullptr);

    // 4.5) hid -> bf16 hi/lo
    convert_hid_kernel<<<NROWS, 256>>>();

    // 5) logits = hid @ W2^T + b2  (cp.async pipelined 3-pass HMMA)
    cudaFuncSetAttribute(logits_mma_kernel,
                         cudaFuncAttributeMaxDynamicSharedMemorySize, SMEM_BIG);
    logits_mma_kernel<<<dim3(NROWS / BM, DVP / BN), 256, SMEM_BIG>>>(b2, out);
}

// round 10
// speedup vs baseline: 1.4443x; 1.3200x over previous
#include <cuda_runtime.h>
#include <cuda_bf16.h>
#include <cuda_fp16.h>
#include <cstdint>

// Problem dims
#define DB 32
#define DT 64
#define DV 50257
#define DVP 50304   // padded vocab (393 * 128)
#define DE 256
#define DH 512
#define G4H 2048   // 4*H
#define H2  1024   // 2*H
#define NROWS 2048 // T*B

// ---------------- scratch (device globals; no allocations allowed) ----------
__device__ float g_xgates[DT * DB * G4H];  // [t*B+b, 4H]
__device__ float g_hgates[DB * G4H];       // [b, 4H]
__device__ float g_hs[DT * DB * DH];       // [t*B+b, H]
__device__ float g_hid[DT * DB * H2];      // [t*B+b, 2H]
// fp16 pre-converted operands for the big GEMM:
//   W2  -> single fp16 (rounding error 2^-11, bounded by rel_err budget)
//   hid -> fp16 hi/lo pair (exact to 2^-22)
__device__ __half g_W2h[(size_t)DVP * H2];
__device__ __half g_hidhi[(size_t)NROWS * H2];
__device__ __half g_hidlo[(size_t)NROWS * H2];

// ---------------- helpers ----------------------------------------------------
__device__ __forceinline__ uint32_t smem_to_u32(const void* smem_ptr) {
    uint32_t addr;
    asm("{ .reg .u64 tmp; cvta.to.shared.u64 tmp, %1; cvt.u32.u64 %0, tmp; }"
        : "=r"(addr) : "l"(smem_ptr));
    return addr;
}

__device__ __forceinline__ void ldmx4(uint32_t* r, uint32_t addr) {
    asm volatile("ldmatrix.sync.aligned.m8n8.x4.shared.b16 {%0,%1,%2,%3}, [%4];"
                 : "=r"(r[0]), "=r"(r[1]), "=r"(r[2]), "=r"(r[3]) : "r"(addr));
}

__device__ __forceinline__ void mma16816(float* c, const uint32_t* a, const uint32_t* b) {
    asm volatile(
        "mma.sync.aligned.m16n8k16.row.col.f32.f16.f16.f32 "
        "{%0,%1,%2,%3}, {%4,%5,%6,%7}, {%8,%9}, {%0,%1,%2,%3};"
        : "+f"(c[0]), "+f"(c[1]), "+f"(c[2]), "+f"(c[3])
        : "r"(a[0]), "r"(a[1]), "r"(a[2]), "r"(a[3]), "r"(b[0]), "r"(b[1]));
}

__device__ __forceinline__ uint32_t pack2h(__half a, __half b) {
    return ((uint32_t)__half_as_ushort(b) << 16) | (uint32_t)__half_as_ushort(a);
}

__device__ __forceinline__ void cp_async16(uint32_t saddr, const void* gaddr) {
    asm volatile("cp.async.cg.shared.global [%0], [%1], 16;"
                 :: "r"(saddr), "l"(gaddr));
}

// XOR swizzle for 64-B rows of 16-B chunks: conflict-free for cp.async stores
// and ldmatrix reads.
__device__ __forceinline__ uint32_t swz(int row, int chunk) {
    return (uint32_t)(row * 64 + ((chunk ^ ((row >> 1) & 3)) << 4));
}

// ---------------- SIMT tiled GEMM: C[m,n] = sum_k A[m,k]*B[n,k] + bias[n] ----
#define SG_BM 64
#define SG_BN 64
#define SG_BK 16

template <bool GATHER>
__global__ __launch_bounds__(256) void sgemm_atbt(
    const float* __restrict__ A, const float* __restrict__ Bw,
    const float* __restrict__ bias, float* __restrict__ C,
    int M, int N, int K, const int* __restrict__ captions)
{
    __shared__ float As[SG_BK][SG_BM + 1];
    __shared__ float Bs[SG_BK][SG_BN + 1];
    const int m0 = blockIdx.y * SG_BM;
    const int n0 = blockIdx.x * SG_BN;
    const int tid = threadIdx.x;
    const int tx = tid & 15, ty = tid >> 4;
    const int arow = tid >> 2;
    const int aq = tid & 3;

    float acc[4][4];
#pragma unroll
    for (int i = 0; i < 4; i++)
#pragma unroll
        for (int j = 0; j < 4; j++) acc[i][j] = 0.f;

    int gm = m0 + arow;
    if (gm > M - 1) gm = M - 1;
    const float* aptr;
    if (GATHER) {
        int t = gm >> 5;
        int b = gm & 31;
        int tt = (t == 0) ? 0 : (t - 1);
        int tok = captions[b * DT + tt];
        aptr = A + (size_t)tok * K;
    } else {
        aptr = A + (size_t)gm * K;
    }
    const float* bptr = Bw + (size_t)(n0 + arow) * K;

    for (int k0 = 0; k0 < K; k0 += SG_BK) {
        float4 av = *(const float4*)(aptr + k0 + aq * 4);
        float4 bv = *(const float4*)(bptr + k0 + aq * 4);
        __syncthreads();
        As[aq * 4 + 0][arow] = av.x; As[aq * 4 + 1][arow] = av.y;
        As[aq * 4 + 2][arow] = av.z; As[aq * 4 + 3][arow] = av.w;
        Bs[aq * 4 + 0][arow] = bv.x; Bs[aq * 4 + 1][arow] = bv.y;
        Bs[aq * 4 + 2][arow] = bv.z; Bs[aq * 4 + 3][arow] = bv.w;
        __syncthreads();
#pragma unroll
        for (int k = 0; k < SG_BK; k++) {
            float a[4], b[4];
#pragma unroll
            for (int i = 0; i < 4; i++) a[i] = As[k][ty * 4 + i];
#pragma unroll
            for (int j = 0; j < 4; j++) b[j] = Bs[k][tx * 4 + j];
#pragma unroll
            for (int i = 0; i < 4; i++)
#pragma unroll
                for (int j = 0; j < 4; j++) acc[i][j] += a[i] * b[j];
        }
    }

#pragma unroll
    for (int i = 0; i < 4; i++) {
        int m = m0 + ty * 4 + i;
        if (m >= M) continue;
#pragma unroll
        for (int j = 0; j < 4; j++) {
            int n = n0 + tx * 4 + j;
            C[(size_t)m * N + n] = acc[i][j] + bias[n];
        }
    }
}

// ---------------- LSTM scan (prefetched; 128-thread blocks for SM spread) ----
__global__ __launch_bounds__(128) void lstm_scan_kernel() {
    int idx = blockIdx.x * 128 + threadIdx.x;  // 0..16383
    int b = idx >> 9;
    int h = idx & (DH - 1);
    const float* hgp = g_hgates + b * G4H;
    float hgi = hgp[h], hgf = hgp[DH + h], hgg = hgp[2 * DH + h], hgo = hgp[3 * DH + h];

    const float* x = g_xgates + (size_t)b * G4H + h;
    const size_t tstride = (size_t)DB * G4H;
    float* hsp = g_hs + (size_t)b * DH + h;
    const size_t hstride = (size_t)DB * DH;

    float xi = x[0], xf = x[DH], xg = x[2 * DH], xo = x[3 * DH];
    float c = 0.f;
#pragma unroll 1
    for (int t = 0; t < DT; t++) {
        float ci = xi, cf = xf, cg = xg, co = xo;
        if (t + 1 < DT) {   // prefetch next step's gates
            const float* xn = x + (size_t)(t + 1) * tstride;
            xi = xn[0]; xf = xn[DH]; xg = xn[2 * DH]; xo = xn[3 * DH];
        }
        float gi = ci + hgi;
        float gf = cf + hgf;
        float gg = cg + hgg;
        float go = co + hgo;
        float si = 1.f / (1.f + expf(-gi));
        float sf = 1.f / (1.f + expf(-gf));
        float so = 1.f / (1.f + expf(-go));
        c = sf * c + si * tanhf(gg);
        hsp[(size_t)t * hstride] = so * tanhf(c);
    }
}

// ---------------- fp32 -> fp16 pre-conversion ---------------------------------
__global__ __launch_bounds__(256) void convert_w2_kernel(const float* __restrict__ W2) {
    int row = blockIdx.x;                // 0..DVP-1
    int q = threadIdx.x * 4;
    size_t o = (size_t)row * H2 + q;
    float4 v = make_float4(0.f, 0.f, 0.f, 0.f);
    if (row < DV) v = *(const float4*)(W2 + o);
    uint2 h = make_uint2(pack2h(__float2half_rn(v.x), __float2half_rn(v.y)),
                         pack2h(__float2half_rn(v.z), __float2half_rn(v.w)));
    *(uint2*)(g_W2h + o) = h;
}

__global__ __launch_bounds__(256) void convert_hid_kernel() {
    int row = blockIdx.x;                // 0..NROWS-1
    int q = threadIdx.x * 4;
    size_t o = (size_t)row * H2 + q;
    float4 v = *(const float4*)(g_hid + o);
    __half hx = __float2half_rn(v.x), hy = __float2half_rn(v.y);
    __half hz = __float2half_rn(v.z), hw = __float2half_rn(v.w);
    uint2 hi = make_uint2(pack2h(hx, hy), pack2h(hz, hw));
    uint2 lo = make_uint2(
        pack2h(__float2half_rn(v.x - __half2float(hx)),
               __float2half_rn(v.y - __half2float(hy))),
        pack2h(__float2half_rn(v.z - __half2float(hz)),
               __float2half_rn(v.w - __half2float(hw))));
    *(uint2*)(g_hidhi + o) = hi;
    *(uint2*)(g_hidlo + o) = lo;
}

// ---------------- big logits GEMM: cp.async pipelined, fp16 2-pass ------------
// C[m, v] = sum_k hid[m,k]*W2[v,k] + b2[v]; A split (hi/lo fp16), B single fp16.
#define BM 128
#define BN 128
#define BK 32
#define NT (H2 / BK)          // 32 K-tiles
// per-stage SMEM (bytes): Ahi 8K | Alo 8K | B 8K = 24 KB
#define ST_ALO 8192
#define ST_B   16384
#define STAGE_BYTES 24576
#define SMEM_BIG (2 * STAGE_BYTES)

__global__ __launch_bounds__(256) void logits_mma_kernel(
    const float* __restrict__ b2, float* __restrict__ out)
{
    extern __shared__ __align__(128) char smem[];
    const uint32_t sb0 = smem_to_u32(smem);
    const int tid = threadIdx.x;
    const int wid = tid >> 5, lane = tid & 31;
    const int m0 = blockIdx.x * BM;
    const int n0 = blockIdx.y * BN;
    const int wm = (wid & 1) * 64;
    const int wn = (wid >> 1) * 32;

    float acc[4][4][4];
#pragma unroll
    for (int mi = 0; mi < 4; mi++)
#pragma unroll
        for (int ni = 0; ni < 4; ni++)
#pragma unroll
            for (int f = 0; f < 4; f++) acc[mi][ni][f] = 0.f;

    const int lrow = tid >> 2;         // 0..63
    const int lc = tid & 3;
    const __half* gAhi = g_hidhi + (size_t)m0 * H2;
    const __half* gAlo = g_hidlo + (size_t)m0 * H2;
    const __half* gB   = g_W2h  + (size_t)n0 * H2;

    const int a_r = lane & 15;
    const int a_cb = lane >> 4;
    const int b_g = lane >> 3;
    const int b_r = (lane & 7) + ((b_g >> 1) * 8);
    const int b_cb = b_g & 1;

    auto issue_stage = [&](int s) {
        const uint32_t base = sb0 + (uint32_t)(s & 1) * STAGE_BYTES;
        const int k0 = s * BK;
#pragma unroll
        for (int j = 0; j < 2; j++) {
            int row = lrow + j * 64;
            uint32_t so = swz(row, lc);
            size_t go = (size_t)row * H2 + k0 + lc * 8;
            cp_async16(base + so,          gAhi + go);
            cp_async16(base + ST_ALO + so, gAlo + go);
            cp_async16(base + ST_B + so,   gB + go);
        }
        asm volatile("cp.async.commit_group;");
    };

    issue_stage(0);

#pragma unroll 1
    for (int s = 0; s < NT; s++) {
        if (s + 1 < NT) {
            issue_stage(s + 1);
            asm volatile("cp.async.wait_group 1;");
        } else {
            asm volatile("cp.async.wait_group 0;");
        }
        __syncthreads();

        const uint32_t base = sb0 + (uint32_t)(s & 1) * STAGE_BYTES;
#pragma unroll
        for (int kk = 0; kk < BK; kk += 16) {
            const int cb = kk >> 3;
            uint32_t ah[4][4], al[4][4], bb[4][2];
#pragma unroll
            for (int mi = 0; mi < 4; mi++) {
                int row = wm + mi * 16 + a_r;
                uint32_t off = swz(row, cb + a_cb);
                ldmx4(ah[mi], base + off);
                ldmx4(al[mi], base + ST_ALO + off);
            }
#pragma unroll
            for (int nb = 0; nb < 2; nb++) {
                int row = wn + nb * 16 + b_r;
                uint32_t off = swz(row, cb + b_cb);
                uint32_t t0[4];
                ldmx4(t0, base + ST_B + off);
                bb[2 * nb][0] = t0[0]; bb[2 * nb][1] = t0[1];
                bb[2 * nb + 1][0] = t0[2]; bb[2 * nb + 1][1] = t0[3];
            }
#pragma unroll
            for (int mi = 0; mi < 4; mi++)
#pragma unroll
                for (int ni = 0; ni < 4; ni++) {
                    mma16816(acc[mi][ni], ah[mi], bb[ni]);
                    mma16816(acc[mi][ni], al[mi], bb[ni]);
                }
        }
        __syncthreads();
    }

    // ---- epilogue: scatter to out[(b*T+t)*V + v] with b2 ----
    const int gr = lane >> 2;
    const int gc = (lane & 3) * 2;
#pragma unroll
    for (int mi = 0; mi < 4; mi++) {
#pragma unroll
        for (int half = 0; half < 2; half++) {
            int m = m0 + wm + mi * 16 + gr + half * 8;
            int t = m >> 5, b = m & 31;
            float* orow = out + (size_t)(b * DT + t) * DV;
#pragma unroll
            for (int ni = 0; ni < 4; ni++) {
                int v = n0 + wn + ni * 8 + gc;
                float c0 = acc[mi][ni][half * 2 + 0];
                float c1 = acc[mi][ni][half * 2 + 1];
                if (v < DV)     orow[v]     = c0 + b2[v];
                if (v + 1 < DV) orow[v + 1] = c1 + b2[v + 1];
            }
        }
    }
}

// ---------------- launch ----------------------------------------------------
extern "C" void kernel_launch(void* const* d_in, const int* in_sizes, int n_in,
                              void* d_out, int out_size) {
    const float* features = (const float*)d_in[0];
    const int*   captions = (const int*)d_in[1];
    const float* emb      = (const float*)d_in[2];
    const float* W_ih     = (const float*)d_in[3];
    const float* W_hh     = (const float*)d_in[4];
    const float* b_ih     = (const float*)d_in[5];
    const float* b_hh     = (const float*)d_in[6];
    const float* W1       = (const float*)d_in[7];
    const float* b1       = (const float*)d_in[8];
    const float* W2       = (const float*)d_in[9];
    const float* b2       = (const float*)d_in[10];
    float* out = (float*)d_out;

    float *xg_p, *hg_p, *hs_p, *hid_p;
    cudaGetSymbolAddress((void**)&xg_p,  g_xgates);
    cudaGetSymbolAddress((void**)&hg_p,  g_hgates);
    cudaGetSymbolAddress((void**)&hs_p,  g_hs);
    cudaGetSymbolAddress((void**)&hid_p, g_hid);

    // 0) W2 -> fp16 (padded to DVP rows)
    convert_w2_kernel<<<DVP, 256>>>(W2);

    // 1) x_gates = emb[tok] @ W_ih^T + b_ih   (2048x2048, K=256)
    sgemm_atbt<true><<<dim3(G4H / SG_BN, NROWS / SG_BM), 256>>>(
        emb, W_ih, b_ih, xg_p, NROWS, G4H, DE, captions);

    // 2) h_gates = features @ W_hh^T + b_hh   (32x2048, K=512)
    sgemm_atbt<false><<<dim3(G4H / SG_BN, 1), 256>>>(
        features, W_hh, b_hh, hg_p, DB, G4H, DH, nullptr);

    // 3) LSTM cell scan
    lstm_scan_kernel<<<DB * DH / 128, 128>>>();

    // 4) hid = hs @ W1^T + b1                 (2048x1024, K=512)
    sgemm_atbt<false><<<dim3(H2 / SG_BN, NROWS / SG_BM), 256>>>(
        hs_p, W1, b1, hid_p, NROWS, H2, DH, nullptr);

    // 4.5) hid -> fp16 hi/lo
    convert_hid_kernel<<<NROWS, 256>>>();

    // 5) logits = hid @ W2^T + b2  (cp.async pipelined fp16 2-pass HMMA)
    cudaFuncSetAttribute(logits_mma_kernel,
                         cudaFuncAttributeMaxDynamicSharedMemorySize, SMEM_BIG);
    logits_mma_kernel<<<dim3(NROWS / BM, DVP / BN), 256, SMEM_BIG>>>(b2, out);
}

// round 13
// speedup vs baseline: 2.0293x; 1.4051x over previous
#include <cuda_runtime.h>
#include <cuda_bf16.h>
#include <cuda_fp16.h>
#include <cstdint>

// Problem dims
#define DB 32
#define DT 64
#define DV 50257
#define DVP 50304   // padded vocab (393 * 128)
#define DE 256
#define DH 512
#define G4H 2048   // 4*H
#define H2  1024   // 2*H
#define NROWS 2048 // T*B

// ---------------- scratch (device globals; no allocations allowed) ----------
__device__ float g_xgates[DT * DB * G4H];  // [t*B+b, 4H]
__device__ float g_hgates[DB * G4H];       // [b, 4H]
__device__ float g_hs[DT * DB * DH];       // [t*B+b, H]
__device__ float g_hid[DT * DB * H2];      // [t*B+b, 2H]
// fp16 pre-converted operands for the big GEMM (single fp16 each; combined
// rounding error ~3e-4 rel, inside the 1e-3 gate)
__device__ __half g_W2h[(size_t)DVP * H2];
__device__ __half g_hidh[(size_t)NROWS * H2];

// ---------------- helpers ----------------------------------------------------
__device__ __forceinline__ uint32_t smem_to_u32(const void* smem_ptr) {
    uint32_t addr;
    asm("{ .reg .u64 tmp; cvta.to.shared.u64 tmp, %1; cvt.u32.u64 %0, tmp; }"
        : "=r"(addr) : "l"(smem_ptr));
    return addr;
}

__device__ __forceinline__ void ldmx4(uint32_t* r, uint32_t addr) {
    asm volatile("ldmatrix.sync.aligned.m8n8.x4.shared.b16 {%0,%1,%2,%3}, [%4];"
                 : "=r"(r[0]), "=r"(r[1]), "=r"(r[2]), "=r"(r[3]) : "r"(addr));
}

__device__ __forceinline__ void mma16816(float* c, const uint32_t* a, const uint32_t* b) {
    asm volatile(
        "mma.sync.aligned.m16n8k16.row.col.f32.f16.f16.f32 "
        "{%0,%1,%2,%3}, {%4,%5,%6,%7}, {%8,%9}, {%0,%1,%2,%3};"
        : "+f"(c[0]), "+f"(c[1]), "+f"(c[2]), "+f"(c[3])
        : "r"(a[0]), "r"(a[1]), "r"(a[2]), "r"(a[3]), "r"(b[0]), "r"(b[1]));
}

__device__ __forceinline__ uint32_t pack2h(__half a, __half b) {
    return ((uint32_t)__half_as_ushort(b) << 16) | (uint32_t)__half_as_ushort(a);
}

__device__ __forceinline__ void cp_async16(uint32_t saddr, const void* gaddr) {
    asm volatile("cp.async.cg.shared.global [%0], [%1], 16;"
                 :: "r"(saddr), "l"(gaddr));
}

// XOR swizzle for 64-B rows of 16-B chunks: conflict-free for cp.async stores
// and ldmatrix reads.
__device__ __forceinline__ uint32_t swz(int row, int chunk) {
    return (uint32_t)(row * 64 + ((chunk ^ ((row >> 1) & 3)) << 4));
}

// ---------------- SIMT tiled GEMM: C[m,n] = sum_k A[m,k]*B[n,k] + bias[n] ----
#define SG_BM 64
#define SG_BN 64
#define SG_BK 16

template <bool GATHER>
__global__ __launch_bounds__(256) void sgemm_atbt(
    const float* __restrict__ A, const float* __restrict__ Bw,
    const float* __restrict__ bias, float* __restrict__ C,
    int M, int N, int K, const int* __restrict__ captions)
{
    __shared__ float As[SG_BK][SG_BM + 1];
    __shared__ float Bs[SG_BK][SG_BN + 1];
    const int m0 = blockIdx.y * SG_BM;
    const int n0 = blockIdx.x * SG_BN;
    const int tid = threadIdx.x;
    const int tx = tid & 15, ty = tid >> 4;
    const int arow = tid >> 2;
    const int aq = tid & 3;

    float acc[4][4];
#pragma unroll
    for (int i = 0; i < 4; i++)
#pragma unroll
        for (int j = 0; j < 4; j++) acc[i][j] = 0.f;

    int gm = m0 + arow;
    if (gm > M - 1) gm = M - 1;
    const float* aptr;
    if (GATHER) {
        int t = gm >> 5;
        int b = gm & 31;
        int tt = (t == 0) ? 0 : (t - 1);
        int tok = captions[b * DT + tt];
        aptr = A + (size_t)tok * K;
    } else {
        aptr = A + (size_t)gm * K;
    }
    const float* bptr = Bw + (size_t)(n0 + arow) * K;

    for (int k0 = 0; k0 < K; k0 += SG_BK) {
        float4 av = *(const float4*)(aptr + k0 + aq * 4);
        float4 bv = *(const float4*)(bptr + k0 + aq * 4);
        __syncthreads();
        As[aq * 4 + 0][arow] = av.x; As[aq * 4 + 1][arow] = av.y;
        As[aq * 4 + 2][arow] = av.z; As[aq * 4 + 3][arow] = av.w;
        Bs[aq * 4 + 0][arow] = bv.x; Bs[aq * 4 + 1][arow] = bv.y;
        Bs[aq * 4 + 2][arow] = bv.z; Bs[aq * 4 + 3][arow] = bv.w;
        __syncthreads();
#pragma unroll
        for (int k = 0; k < SG_BK; k++) {
            float a[4], b[4];
#pragma unroll
            for (int i = 0; i < 4; i++) a[i] = As[k][ty * 4 + i];
#pragma unroll
            for (int j = 0; j < 4; j++) b[j] = Bs[k][tx * 4 + j];
#pragma unroll
            for (int i = 0; i < 4; i++)
#pragma unroll
                for (int j = 0; j < 4; j++) acc[i][j] += a[i] * b[j];
        }
    }

#pragma unroll
    for (int i = 0; i < 4; i++) {
        int m = m0 + ty * 4 + i;
        if (m >= M) continue;
#pragma unroll
        for (int j = 0; j < 4; j++) {
            int n = n0 + tx * 4 + j;
            C[(size_t)m * N + n] = acc[i][j] + bias[n];
        }
    }
}

// ---------------- LSTM scan (prefetched; 128-thread blocks for SM spread) ----
__global__ __launch_bounds__(128) void lstm_scan_kernel() {
    int idx = blockIdx.x * 128 + threadIdx.x;  // 0..16383
    int b = idx >> 9;
    int h = idx & (DH - 1);
    const float* hgp = g_hgates + b * G4H;
    float hgi = hgp[h], hgf = hgp[DH + h], hgg = hgp[2 * DH + h], hgo = hgp[3 * DH + h];

    const float* x = g_xgates + (size_t)b * G4H + h;
    const size_t tstride = (size_t)DB * G4H;
    float* hsp = g_hs + (size_t)b * DH + h;
    const size_t hstride = (size_t)DB * DH;

    float xi = x[0], xf = x[DH], xg = x[2 * DH], xo = x[3 * DH];
    float c = 0.f;
#pragma unroll 1
    for (int t = 0; t < DT; t++) {
        float ci = xi, cf = xf, cg = xg, co = xo;
        if (t + 1 < DT) {   // prefetch next step's gates
            const float* xn = x + (size_t)(t + 1) * tstride;
            xi = xn[0]; xf = xn[DH]; xg = xn[2 * DH]; xo = xn[3 * DH];
        }
        float gi = ci + hgi;
        float gf = cf + hgf;
        float gg = cg + hgg;
        float go = co + hgo;
        float si = 1.f / (1.f + expf(-gi));
        float sf = 1.f / (1.f + expf(-gf));
        float so = 1.f / (1.f + expf(-go));
        c = sf * c + si * tanhf(gg);
        hsp[(size_t)t * hstride] = so * tanhf(c);
    }
}

// ---------------- fp32 -> fp16 pre-conversion ---------------------------------
__global__ __launch_bounds__(256) void convert_w2_kernel(const float* __restrict__ W2) {
    int row = blockIdx.x;                // 0..DVP-1
    int q = threadIdx.x * 4;
    size_t o = (size_t)row * H2 + q;
    float4 v = make_float4(0.f, 0.f, 0.f, 0.f);
    if (row < DV) v = *(const float4*)(W2 + o);
    uint2 h = make_uint2(pack2h(__float2half_rn(v.x), __float2half_rn(v.y)),
                         pack2h(__float2half_rn(v.z), __float2half_rn(v.w)));
    *(uint2*)(g_W2h + o) = h;
}

__global__ __launch_bounds__(256) void convert_hid_kernel() {
    int row = blockIdx.x;                // 0..NROWS-1
    int q = threadIdx.x * 4;
    size_t o = (size_t)row * H2 + q;
    float4 v = *(const float4*)(g_hid + o);
    uint2 h = make_uint2(pack2h(__float2half_rn(v.x), __float2half_rn(v.y)),
                         pack2h(__float2half_rn(v.z), __float2half_rn(v.w)));
    *(uint2*)(g_hidh + o) = h;
}

// ---------------- big logits GEMM: cp.async pipelined, fp16 single-pass -------
// C[m, v] = sum_k hid[m,k]*W2[v,k] + b2[v]
#define BM 128
#define BN 128
#define BK 32
#define NT (H2 / BK)          // 32 K-tiles
// per-stage SMEM (bytes): A 8K | B 8K = 16 KB
#define ST_B   8192
#define STAGE_BYTES 16384
#define SMEM_BIG (2 * STAGE_BYTES)

__global__ __launch_bounds__(256) void logits_mma_kernel(
    const float* __restrict__ b2, float* __restrict__ out)
{
    extern __shared__ __align__(128) char smem[];
    const uint32_t sb0 = smem_to_u32(smem);
    const int tid = threadIdx.x;
    const int wid = tid >> 5, lane = tid & 31;
    const int m0 = blockIdx.x * BM;
    const int n0 = blockIdx.y * BN;
    const int wm = (wid & 1) * 64;
    const int wn = (wid >> 1) * 32;

    float acc[4][4][4];
#pragma unroll
    for (int mi = 0; mi < 4; mi++)
#pragma unroll
        for (int ni = 0; ni < 4; ni++)
#pragma unroll
            for (int f = 0; f < 4; f++) acc[mi][ni][f] = 0.f;

    const int lrow = tid >> 2;         // 0..63
    const int lc = tid & 3;
    const __half* gA = g_hidh + (size_t)m0 * H2;
    const __half* gB = g_W2h  + (size_t)n0 * H2;

    const int a_r = lane & 15;
    const int a_cb = lane >> 4;
    const int b_g = lane >> 3;
    const int b_r = (lane & 7) + ((b_g >> 1) * 8);
    const int b_cb = b_g & 1;

    auto issue_stage = [&](int s) {
        const uint32_t base = sb0 + (uint32_t)(s & 1) * STAGE_BYTES;
        const int k0 = s * BK;
#pragma unroll
        for (int j = 0; j < 2; j++) {
            int row = lrow + j * 64;
            uint32_t so = swz(row, lc);
            size_t go = (size_t)row * H2 + k0 + lc * 8;
            cp_async16(base + so,        gA + go);
            cp_async16(base + ST_B + so, gB + go);
        }
        asm volatile("cp.async.commit_group;");
    };

    issue_stage(0);

#pragma unroll 1
    for (int s = 0; s < NT; s++) {
        if (s + 1 < NT) {
            issue_stage(s + 1);
            asm volatile("cp.async.wait_group 1;");
        } else {
            asm volatile("cp.async.wait_group 0;");
        }
        __syncthreads();

        const uint32_t base = sb0 + (uint32_t)(s & 1) * STAGE_BYTES;
#pragma unroll
        for (int kk = 0; kk < BK; kk += 16) {
            const int cb = kk >> 3;
            uint32_t ah[4][4], bb[4][2];
#pragma unroll
            for (int mi = 0; mi < 4; mi++) {
                int row = wm + mi * 16 + a_r;
                uint32_t off = swz(row, cb + a_cb);
                ldmx4(ah[mi], base + off);
            }
#pragma unroll
            for (int nb = 0; nb < 2; nb++) {
                int row = wn + nb * 16 + b_r;
                uint32_t off = swz(row, cb + b_cb);
                uint32_t t0[4];
                ldmx4(t0, base + ST_B + off);
                bb[2 * nb][0] = t0[0]; bb[2 * nb][1] = t0[1];
                bb[2 * nb + 1][0] = t0[2]; bb[2 * nb + 1][1] = t0[3];
            }
#pragma unroll
            for (int mi = 0; mi < 4; mi++)
#pragma unroll
                for (int ni = 0; ni < 4; ni++)
                    mma16816(acc[mi][ni], ah[mi], bb[ni]);
        }
        __syncthreads();
    }

    // ---- epilogue: scatter to out[(b*T+t)*V + v] with b2 ----
    const int gr = lane >> 2;
    const int gc = (lane & 3) * 2;
#pragma unroll
    for (int mi = 0; mi < 4; mi++) {
#pragma unroll
        for (int half = 0; half < 2; half++) {
            int m = m0 + wm + mi * 16 + gr + half * 8;
            int t = m >> 5, b = m & 31;
            float* orow = out + (size_t)(b * DT + t) * DV;
#pragma unroll
            for (int ni = 0; ni < 4; ni++) {
                int v = n0 + wn + ni * 8 + gc;
                float c0 = acc[mi][ni][half * 2 + 0];
                float c1 = acc[mi][ni][half * 2 + 1];
                if (v < DV)     orow[v]     = c0 + b2[v];
                if (v + 1 < DV) orow[v + 1] = c1 + b2[v + 1];
            }
        }
    }
}

// ---------------- launch ----------------------------------------------------
extern "C" void kernel_launch(void* const* d_in, const int* in_sizes, int n_in,
                              void* d_out, int out_size) {
    const float* features = (const float*)d_in[0];
    const int*   captions = (const int*)d_in[1];
    const float* emb      = (const float*)d_in[2];
    const float* W_ih     = (const float*)d_in[3];
    const float* W_hh     = (const float*)d_in[4];
    const float* b_ih     = (const float*)d_in[5];
    const float* b_hh     = (const float*)d_in[6];
    const float* W1       = (const float*)d_in[7];
    const float* b1       = (const float*)d_in[8];
    const float* W2       = (const float*)d_in[9];
    const float* b2       = (const float*)d_in[10];
    float* out = (float*)d_out;

    float *xg_p, *hg_p, *hs_p, *hid_p;
    cudaGetSymbolAddress((void**)&xg_p,  g_xgates);
    cudaGetSymbolAddress((void**)&hg_p,  g_hgates);
    cudaGetSymbolAddress((void**)&hs_p,  g_hs);
    cudaGetSymbolAddress((void**)&hid_p, g_hid);

    // 0) W2 -> fp16 (padded to DVP rows)
    convert_w2_kernel<<<DVP, 256>>>(W2);

    // 1) x_gates = emb[tok] @ W_ih^T + b_ih   (2048x2048, K=256)
    sgemm_atbt<true><<<dim3(G4H / SG_BN, NROWS / SG_BM), 256>>>(
        emb, W_ih, b_ih, xg_p, NROWS, G4H, DE, captions);

    // 2) h_gates = features @ W_hh^T + b_hh   (32x2048, K=512)
    sgemm_atbt<false><<<dim3(G4H / SG_BN, 1), 256>>>(
        features, W_hh, b_hh, hg_p, DB, G4H, DH, nullptr);

    // 3) LSTM cell scan
    lstm_scan_kernel<<<DB * DH / 128, 128>>>();

    // 4) hid = hs @ W1^T + b1                 (2048x1024, K=512)
    sgemm_atbt<false><<<dim3(H2 / SG_BN, NROWS / SG_BM), 256>>>(
        hs_p, W1, b1, hid_p, NROWS, H2, DH, nullptr);

    // 4.5) hid -> fp16
    convert_hid_kernel<<<NROWS, 256>>>();

    // 5) logits = hid @ W2^T + b2  (cp.async pipelined fp16 single-pass HMMA)
    cudaFuncSetAttribute(logits_mma_kernel,
                         cudaFuncAttributeMaxDynamicSharedMemorySize, SMEM_BIG);
    logits_mma_kernel<<<dim3(NROWS / BM, DVP / BN), 256, SMEM_BIG>>>(b2, out);
}

// round 15
// speedup vs baseline: 2.5691x; 1.2660x over previous
#include <cuda_runtime.h>
#include <cuda_bf16.h>
#include <cuda_fp16.h>
#include <cstdint>

// Problem dims
#define DB 32
#define DT 64
#define DV 50257
#define DVP 50304   // padded vocab (393 * 128)
#define DE 256
#define DH 512
#define G4H 2048   // 4*H
#define H2  1024   // 2*H
#define NROWS 2048 // T*B

// ---------------- scratch (device globals; no allocations allowed) ----------
__device__ float g_xgates[DT * DB * G4H];            // [t*B+b, 4H] fp32
__device__ float g_hgates[DB * G4H];                 // [b, 4H] fp32
__device__ __half g_hsh[NROWS * DH];                 // hs fp16 [t*B+b, H]
__device__ __half g_W2h[(size_t)DVP * H2];           // W2 fp16 (zero-padded rows)
__device__ __half g_W1t[DH * H2];                    // W1^T fp16 [H, 2H]
__device__ __half g_Wfh[(size_t)DVP * DH];           // Wf = W2@W1 fp16 [V, H]
__device__ float  g_b2f[DVP];                        // b2 + W2@b1
__device__ __half g_xseqh[NROWS * DE];               // gathered emb rows fp16
__device__ __half g_Wihh[G4H * DE];                  // W_ih fp16

// ---------------- helpers ----------------------------------------------------
__device__ __forceinline__ uint32_t smem_to_u32(const void* smem_ptr) {
    uint32_t addr;
    asm("{ .reg .u64 tmp; cvta.to.shared.u64 tmp, %1; cvt.u32.u64 %0, tmp; }"
        : "=r"(addr) : "l"(smem_ptr));
    return addr;
}

__device__ __forceinline__ void ldmx4(uint32_t* r, uint32_t addr) {
    asm volatile("ldmatrix.sync.aligned.m8n8.x4.shared.b16 {%0,%1,%2,%3}, [%4];"
                 : "=r"(r[0]), "=r"(r[1]), "=r"(r[2]), "=r"(r[3]) : "r"(addr));
}

__device__ __forceinline__ void mma16816(float* c, const uint32_t* a, const uint32_t* b) {
    asm volatile(
        "mma.sync.aligned.m16n8k16.row.col.f32.f16.f16.f32 "
        "{%0,%1,%2,%3}, {%4,%5,%6,%7}, {%8,%9}, {%0,%1,%2,%3};"
        : "+f"(c[0]), "+f"(c[1]), "+f"(c[2]), "+f"(c[3])
        : "r"(a[0]), "r"(a[1]), "r"(a[2]), "r"(a[3]), "r"(b[0]), "r"(b[1]));
}

__device__ __forceinline__ uint32_t pack2h(__half a, __half b) {
    return ((uint32_t)__half_as_ushort(b) << 16) | (uint32_t)__half_as_ushort(a);
}

__device__ __forceinline__ void cp_async16(uint32_t saddr, const void* gaddr) {
    asm volatile("cp.async.cg.shared.global [%0], [%1], 16;"
                 :: "r"(saddr), "l"(gaddr));
}

// XOR swizzle: conflict-free for cp.async stores and ldmatrix reads.
__device__ __forceinline__ uint32_t swz(int row, int chunk) {
    return (uint32_t)(row * 64 + ((chunk ^ ((row >> 1) & 3)) << 4));
}

__device__ __forceinline__ float fsig(float x) {
    return __fdividef(1.f, 1.f + __expf(-x));
}
__device__ __forceinline__ float ftanh(float x) {
    return __fdividef(2.f, 1.f + __expf(-2.f * x)) - 1.f;
}

// ---------------- SIMT tiled GEMM (h_gates only: M=32) ----------------------
#define SG_BM 64
#define SG_BN 64
#define SG_BK 16

__global__ __launch_bounds__(256) void sgemm_hgates(
    const float* __restrict__ A, const float* __restrict__ Bw,
    const float* __restrict__ bias, float* __restrict__ C,
    int M, int N, int K)
{
    __shared__ float As[SG_BK][SG_BM + 1];
    __shared__ float Bs[SG_BK][SG_BN + 1];
    const int n0 = blockIdx.x * SG_BN;
    const int tid = threadIdx.x;
    const int tx = tid & 15, ty = tid >> 4;
    const int arow = tid >> 2;
    const int aq = tid & 3;

    float acc[4][4];
#pragma unroll
    for (int i = 0; i < 4; i++)
#pragma unroll
        for (int j = 0; j < 4; j++) acc[i][j] = 0.f;

    int gm = arow; if (gm > M - 1) gm = M - 1;
    const float* aptr = A + (size_t)gm * K;
    const float* bptr = Bw + (size_t)(n0 + arow) * K;

    for (int k0 = 0; k0 < K; k0 += SG_BK) {
        float4 av = *(const float4*)(aptr + k0 + aq * 4);
        float4 bv = *(const float4*)(bptr + k0 + aq * 4);
        __syncthreads();
        As[aq * 4 + 0][arow] = av.x; As[aq * 4 + 1][arow] = av.y;
        As[aq * 4 + 2][arow] = av.z; As[aq * 4 + 3][arow] = av.w;
        Bs[aq * 4 + 0][arow] = bv.x; Bs[aq * 4 + 1][arow] = bv.y;
        Bs[aq * 4 + 2][arow] = bv.z; Bs[aq * 4 + 3][arow] = bv.w;
        __syncthreads();
#pragma unroll
        for (int k = 0; k < SG_BK; k++) {
            float a[4], b[4];
#pragma unroll
            for (int i = 0; i < 4; i++) a[i] = As[k][ty * 4 + i];
#pragma unroll
            for (int j = 0; j < 4; j++) b[j] = Bs[k][tx * 4 + j];
#pragma unroll
            for (int i = 0; i < 4; i++)
#pragma unroll
                for (int j = 0; j < 4; j++) acc[i][j] += a[i] * b[j];
        }
    }

#pragma unroll
    for (int i = 0; i < 4; i++) {
        int m = ty * 4 + i;
        if (m >= M) continue;
#pragma unroll
        for (int j = 0; j < 4; j++) {
            int n = n0 + tx * 4 + j;
            C[(size_t)m * N + n] = acc[i][j] + bias[n];
        }
    }
}

// ---------------- LSTM scan: depth-2 prefetch, fast-math, fp16 hs out --------
__global__ __launch_bounds__(128) void lstm_scan_kernel() {
    int idx = blockIdx.x * 128 + threadIdx.x;  // 0..16383
    int b = idx >> 9;
    int h = idx & (DH - 1);
    const float* hgp = g_hgates + b * G4H;
    float hgi = hgp[h], hgf = hgp[DH + h], hgg = hgp[2 * DH + h], hgo = hgp[3 * DH + h];

    const float* x = g_xgates + (size_t)b * G4H + h;
    const size_t tstride = (size_t)DB * G4H;
    __half* hsp = g_hsh + (size_t)b * DH + h;
    const size_t hstride = (size_t)DB * DH;

    float ai[2], af[2], ag[2], ao[2];
#pragma unroll
    for (int p = 0; p < 2; p++) {
        const float* xp = x + (size_t)p * tstride;
        ai[p] = xp[0]; af[p] = xp[DH]; ag[p] = xp[2 * DH]; ao[p] = xp[3 * DH];
    }
    float c = 0.f;
#pragma unroll 1
    for (int t = 0; t < DT; t++) {
        int p = t & 1;
        float gi = ai[p] + hgi;
        float gf = af[p] + hgf;
        float gg = ag[p] + hgg;
        float go = ao[p] + hgo;
        if (t + 2 < DT) {
            const float* xn = x + (size_t)(t + 2) * tstride;
            ai[p] = xn[0]; af[p] = xn[DH]; ag[p] = xn[2 * DH]; ao[p] = xn[3 * DH];
        }
        c = fsig(gf) * c + fsig(gi) * ftanh(gg);
        hsp[(size_t)t * hstride] = __float2half_rn(fsig(go) * ftanh(c));
    }
}

// ---------------- conversion / gather kernels ---------------------------------
__global__ __launch_bounds__(256) void convert_w2_kernel(const float* __restrict__ W2) {
    int row = blockIdx.x;                // 0..DVP-1
    int q = threadIdx.x * 4;
    size_t o = (size_t)row * H2 + q;
    float4 v = make_float4(0.f, 0.f, 0.f, 0.f);
    if (row < DV) v = *(const float4*)(W2 + o);
    uint2 h = make_uint2(pack2h(__float2half_rn(v.x), __float2half_rn(v.y)),
                         pack2h(__float2half_rn(v.z), __float2half_rn(v.w)));
    *(uint2*)(g_W2h + o) = h;
}

// W1 [2H, H] -> W1^T fp16 [H, 2H]
__global__ __launch_bounds__(256) void convert_w1t_kernel(const float* __restrict__ W1) {
    int h = blockIdx.x;                  // 0..DH-1
    int k0 = threadIdx.x * 4;            // 0..1023 step
    __half* dst = g_W1t + (size_t)h * H2 + k0;
#pragma unroll
    for (int j = 0; j < 4; j++)
        dst[j] = __float2half_rn(W1[(size_t)(k0 + j) * DH + h]);
}

// b2f[v] = b2[v] + sum_k W2h[v,k]*b1[k]   (warp per row)
__global__ __launch_bounds__(256) void b2f_kernel(const float* __restrict__ b1,
                                                  const float* __restrict__ b2) {
    int row = blockIdx.x * 8 + (threadIdx.x >> 5);
    int lane = threadIdx.x & 31;
    if (row >= DVP) return;
    const __half* w = g_W2h + (size_t)row * H2;
    float s = 0.f;
#pragma unroll 4
    for (int k = lane * 2; k < H2; k += 64) {
        float2 f = __half22float2(*(const __half2*)(w + k));
        s += f.x * b1[k] + f.y * b1[k + 1];
    }
#pragma unroll
    for (int o = 16; o; o >>= 1) s += __shfl_xor_sync(0xffffffffu, s, o);
    if (lane == 0) g_b2f[row] = (row < DV) ? (s + b2[row]) : 0.f;
}

// x_seq gather + fp16 convert: row m=t*B+b <- emb[tok(b, t?t-1:0)]
__global__ __launch_bounds__(64) void gather_xseq_kernel(
    const float* __restrict__ emb, const int* __restrict__ captions) {
    int m = blockIdx.x;
    int t = m >> 5, b = m & 31;
    int tt = t ? (t - 1) : 0;
    int tok = captions[b * DT + tt];
    const float* src = emb + (size_t)tok * DE;
    int q = threadIdx.x * 4;
    float4 v = *(const float4*)(src + q);
    uint2 h = make_uint2(pack2h(__float2half_rn(v.x), __float2half_rn(v.y)),
                         pack2h(__float2half_rn(v.z), __float2half_rn(v.w)));
    *(uint2*)(g_xseqh + (size_t)m * DE + q) = h;
}

__global__ __launch_bounds__(64) void convert_wih_kernel(const float* __restrict__ W_ih) {
    int row = blockIdx.x;                // 0..G4H-1
    int q = threadIdx.x * 4;
    size_t o = (size_t)row * DE + q;
    float4 v = *(const float4*)(W_ih + o);
    uint2 h = make_uint2(pack2h(__float2half_rn(v.x), __float2half_rn(v.y)),
                         pack2h(__float2half_rn(v.z), __float2half_rn(v.w)));
    *(uint2*)(g_Wihh + o) = h;
}

// ---------------- generic fp16 HMMA GEMM: C[m,n] = sum_k A[m,k]*B[n,k] -------
// OUT=0: fp32 row-major + bias. OUT=1: fp16 row-major, no bias.
// OUT=2: logits scatter out[(b*T+t)*V + v] = acc + bias[v], m = t*B+b.
#define BM 128
#define BN 128
#define BK 32
#define ST_B   8192
#define STAGE_BYTES 16384
#define SMEM_BIG (2 * STAGE_BYTES)

template <int OUT>
__global__ __launch_bounds__(256) void hgemm_kernel(
    const __half* __restrict__ A, const __half* __restrict__ Bm,
    const float* __restrict__ bias, void* __restrict__ outv,
    int K, int Ncols)
{
    extern __shared__ __align__(128) char smem[];
    const uint32_t sb0 = smem_to_u32(smem);
    const int tid = threadIdx.x;
    const int wid = tid >> 5, lane = tid & 31;
    const int m0 = blockIdx.x * BM;
    const int n0 = blockIdx.y * BN;
    const int wm = (wid & 1) * 64;
    const int wn = (wid >> 1) * 32;
    const int NT = K >> 5;

    float acc[4][4][4];
#pragma unroll
    for (int mi = 0; mi < 4; mi++)
#pragma unroll
        for (int ni = 0; ni < 4; ni++)
#pragma unroll
            for (int f = 0; f < 4; f++) acc[mi][ni][f] = 0.f;

    const int lrow = tid >> 2;         // 0..63
    const int lc = tid & 3;
    const __half* gA = A + (size_t)m0 * K;
    const __half* gB = Bm + (size_t)n0 * K;

    const int a_r = lane & 15;
    const int a_cb = lane >> 4;
    const int b_g = lane >> 3;
    const int b_r = (lane & 7) + ((b_g >> 1) * 8);
    const int b_cb = b_g & 1;

    auto issue_stage = [&](int s) {
        const uint32_t base = sb0 + (uint32_t)(s & 1) * STAGE_BYTES;
        const int k0 = s * BK;
#pragma unroll
        for (int j = 0; j < 2; j++) {
            int row = lrow + j * 64;
            uint32_t so = swz(row, lc);
            size_t go = (size_t)row * K + k0 + lc * 8;
            cp_async16(base + so,        gA + go);
            cp_async16(base + ST_B + so, gB + go);
        }
        asm volatile("cp.async.commit_group;");
    };

    issue_stage(0);

#pragma unroll 1
    for (int s = 0; s < NT; s++) {
        if (s + 1 < NT) {
            issue_stage(s + 1);
            asm volatile("cp.async.wait_group 1;");
        } else {
            asm volatile("cp.async.wait_group 0;");
        }
        __syncthreads();

        const uint32_t base = sb0 + (uint32_t)(s & 1) * STAGE_BYTES;
#pragma unroll
        for (int kk = 0; kk < BK; kk += 16) {
            const int cb = kk >> 3;
            uint32_t ah[4][4], bb[4][2];
#pragma unroll
            for (int mi = 0; mi < 4; mi++) {
                int row = wm + mi * 16 + a_r;
                ldmx4(ah[mi], base + swz(row, cb + a_cb));
            }
#pragma unroll
            for (int nb = 0; nb < 2; nb++) {
                int row = wn + nb * 16 + b_r;
                uint32_t t0[4];
                ldmx4(t0, base + ST_B + swz(row, cb + b_cb));
                bb[2 * nb][0] = t0[0]; bb[2 * nb][1] = t0[1];
                bb[2 * nb + 1][0] = t0[2]; bb[2 * nb + 1][1] = t0[3];
            }
#pragma unroll
            for (int mi = 0; mi < 4; mi++)
#pragma unroll
                for (int ni = 0; ni < 4; ni++)
                    mma16816(acc[mi][ni], ah[mi], bb[ni]);
        }
        __syncthreads();
    }

    // ---- epilogue ----
    const int gr = lane >> 2;
    const int gc = (lane & 3) * 2;
#pragma unroll
    for (int mi = 0; mi < 4; mi++) {
#pragma unroll
        for (int half = 0; half < 2; half++) {
            int m = m0 + wm + mi * 16 + gr + half * 8;
#pragma unroll
            for (int ni = 0; ni < 4; ni++) {
                int n = n0 + wn + ni * 8 + gc;
                float c0 = acc[mi][ni][half * 2 + 0];
                float c1 = acc[mi][ni][half * 2 + 1];
                if (OUT == 0) {
                    float2 o = make_float2(c0 + bias[n], c1 + bias[n + 1]);
                    *(float2*)((float*)outv + (size_t)m * Ncols + n) = o;
                } else if (OUT == 1) {
                    __half2 o = __floats2half2_rn(c0, c1);
                    *(__half2*)((__half*)outv + (size_t)m * Ncols + n) = o;
                } else {
                    int t = m >> 5, b = m & 31;
                    float* orow = (float*)outv + (size_t)(b * DT + t) * DV;
                    if (n < DV)     orow[n]     = c0 + bias[n];
                    if (n + 1 < DV) orow[n + 1] = c1 + bias[n + 1];
                }
            }
        }
    }
}

// ---------------- launch ----------------------------------------------------
extern "C" void kernel_launch(void* const* d_in, const int* in_sizes, int n_in,
                              void* d_out, int out_size) {
    const float* features = (const float*)d_in[0];
    const int*   captions = (const int*)d_in[1];
    const float* emb      = (const float*)d_in[2];
    const float* W_ih     = (const float*)d_in[3];
    const float* W_hh     = (const float*)d_in[4];
    const float* b_ih     = (const float*)d_in[5];
    const float* b_hh     = (const float*)d_in[6];
    const float* W1       = (const float*)d_in[7];
    const float* b1       = (const float*)d_in[8];
    const float* W2       = (const float*)d_in[9];
    const float* b2       = (const float*)d_in[10];
    float* out = (float*)d_out;

    float *xg_p, *hg_p;
    __half *w2h_p, *w1t_p, *wfh_p, *xsq_p, *wih_p, *hsh_p;
    float *b2f_p;
    cudaGetSymbolAddress((void**)&xg_p,  g_xgates);
    cudaGetSymbolAddress((void**)&hg_p,  g_hgates);
    cudaGetSymbolAddress((void**)&w2h_p, g_W2h);
    cudaGetSymbolAddress((void**)&w1t_p, g_W1t);
    cudaGetSymbolAddress((void**)&wfh_p, g_Wfh);
    cudaGetSymbolAddress((void**)&xsq_p, g_xseqh);
    cudaGetSymbolAddress((void**)&wih_p, g_Wihh);
    cudaGetSymbolAddress((void**)&hsh_p, g_hsh);
    cudaGetSymbolAddress((void**)&b2f_p, g_b2f);

    cudaFuncSetAttribute(hgemm_kernel<0>, cudaFuncAttributeMaxDynamicSharedMemorySize, SMEM_BIG);
    cudaFuncSetAttribute(hgemm_kernel<1>, cudaFuncAttributeMaxDynamicSharedMemorySize, SMEM_BIG);
    cudaFuncSetAttribute(hgemm_kernel<2>, cudaFuncAttributeMaxDynamicSharedMemorySize, SMEM_BIG);

    // weight preprocessing
    convert_w2_kernel<<<DVP, 256>>>(W2);
    convert_w1t_kernel<<<DH, 256>>>(W1);
    // fold: Wf[v,h] = sum_k W2[v,k] * W1[k,h]   (M=DVP, N=DH, K=2H)
    hgemm_kernel<1><<<dim3(DVP / BM, DH / BN), 256, SMEM_BIG>>>(
        w2h_p, w1t_p, nullptr, wfh_p, H2, DH);
    b2f_kernel<<<DVP / 8, 256>>>(b1, b2);

    // x path
    gather_xseq_kernel<<<NROWS, 64>>>(emb, captions);
    convert_wih_kernel<<<G4H, 64>>>(W_ih);
    // x_gates = x_seq @ W_ih^T + b_ih  (M=2048, N=2048, K=256)
    hgemm_kernel<0><<<dim3(NROWS / BM, G4H / BN), 256, SMEM_BIG>>>(
        xsq_p, wih_p, b_ih, xg_p, DE, G4H);

    // h_gates = features @ W_hh^T + b_hh  (32x2048, K=512)
    sgemm_hgates<<<dim3(G4H / SG_BN, 1), 256>>>(
        features, W_hh, b_hh, hg_p, DB, G4H, DH);

    // LSTM scan (writes hs fp16)
    lstm_scan_kernel<<<DB * DH / 128, 128>>>();

    // logits = hs @ Wf^T + b2f  (M=2048, N=DVP, K=512)
    hgemm_kernel<2><<<dim3(NROWS / BM, DVP / BN), 256, SMEM_BIG>>>(
        hsh_p, wfh_p, b2f_p, out, DH, 0);
}